// round 4
// baseline (speedup 1.0000x reference)
#include <cuda_runtime.h>
#include <cstdint>

#define DF 128          // feature dim
#define DH 512          // hidden dim
#define MAXN 10000      // nodes
#define MAXG 128        // >= n_graphs (100)
#define EPW 32          // edges per warp strip

// -------- static device scratch (no allocations allowed) --------
__device__ float g_tmp[MAXN * DH];    // relu(nodes@W1+b1)
__device__ float g_h[MAXN * DF];      // final node features (L2-resident, 5.1MB)
__device__ float g_wsum[MAXG];
__device__ float g_esum[MAXG];
__device__ int   g_eoff[MAXG + 1];
__device__ int   g_nid[MAXG];

// ============================================================================
// Kernel 0: prefix sums + zero accumulators (runs every replay)
// ============================================================================
__global__ void prefix_kernel(const int* __restrict__ n_node,
                              const int* __restrict__ n_edge, int G) {
    int t = threadIdx.x;
    if (t < MAXG) { g_wsum[t] = 0.f; g_esum[t] = 0.f; }
    if (t == 0) {
        int ea = 0, na = 0;
        g_eoff[0] = 0;
        for (int g = 0; g < G; g++) {
            ea += n_edge[g]; g_eoff[g + 1] = ea;
            na += n_node[g]; g_nid[g] = na - 1;
        }
    }
}

// ============================================================================
// Packed-fp32 (fma.rn.f32x2) tiled SGEMM: C = act(A@B + bias)
// Tile: BM=64 x BN=128, BK=32, 256 threads, 4x8 micro-tile per thread.
// A stored transposed + DUPLICATED in smem -> LDS.64 gives (a,a).
// B stored naturally -> LDS.128 gives two (b_j, b_{j+1}) pairs.
// 16 FFMA2 per k per thread = 32 fp32 FMA. Bit-exact fp32.
// ============================================================================
#define BM 64
#define BN 128
#define BK 32
#define AST (2 * BM + 2)   // dup row stride (words). even -> 8B aligned; +2 de-banks STS

__device__ __forceinline__ void ffma2(unsigned long long& d,
                                      unsigned long long a,
                                      unsigned long long b) {
    asm("fma.rn.f32x2 %0, %1, %2, %0;" : "+l"(d) : "l"(a), "l"(b));
}

__global__ __launch_bounds__(256)
void gemm_bias_act(const float* __restrict__ A, const float* __restrict__ B,
                   const float* __restrict__ bias, float* __restrict__ C,
                   int M, int N, int K, int doRelu) {
    __shared__ float Astd[BK][AST];    // Astd[k][2m] = Astd[k][2m+1] = A[row0+m][k0+k]
    __shared__ float Bs[BK][BN];       // natural

    int tid = threadIdx.x;
    int tx = tid & 15;                 // col group: cols tx*8 .. tx*8+7
    int ty = tid >> 4;                 // row group: rows ty*4 .. ty*4+3
    int row0 = blockIdx.y * BM;
    int col0 = blockIdx.x * BN;

    unsigned long long acc[4][4];      // [row][colpair] -> (C[r][2p], C[r][2p+1])
    #pragma unroll
    for (int i = 0; i < 4; i++)
        #pragma unroll
        for (int j = 0; j < 4; j++) acc[i][j] = 0ull;

    for (int k0 = 0; k0 < K; k0 += BK) {
        // --- A tile: 64x32 floats, transpose + duplicate ---
        #pragma unroll
        for (int i = 0; i < 2; i++) {
            int lin = tid + i * 256;
            int r = lin >> 3;              // 0..63
            int c4 = (lin & 7) * 4;        // k within tile
            int row = row0 + r;
            float4 v = make_float4(0.f, 0.f, 0.f, 0.f);
            if (row < M)
                v = *(const float4*)(A + (size_t)row * K + k0 + c4);
            *(float2*)&Astd[c4 + 0][2 * r] = make_float2(v.x, v.x);
            *(float2*)&Astd[c4 + 1][2 * r] = make_float2(v.y, v.y);
            *(float2*)&Astd[c4 + 2][2 * r] = make_float2(v.z, v.z);
            *(float2*)&Astd[c4 + 3][2 * r] = make_float2(v.w, v.w);
        }
        // --- B tile: 32x128 floats, natural ---
        #pragma unroll
        for (int i = 0; i < 4; i++) {
            int lin = tid + i * 256;
            int kk = lin >> 5;             // 0..31
            int c4 = (lin & 31) * 4;       // 0..124
            float4 v = *(const float4*)(B + (size_t)(k0 + kk) * N + col0 + c4);
            *(float4*)&Bs[kk][c4] = v;
        }
        __syncthreads();

        #pragma unroll 8
        for (int k = 0; k < BK; k++) {
            unsigned long long ad[4];
            #pragma unroll
            for (int i = 0; i < 4; i++)
                ad[i] = *(const unsigned long long*)&Astd[k][2 * (ty * 4 + i)];
            ulonglong2 b01 = *(const ulonglong2*)&Bs[k][tx * 8];
            ulonglong2 b23 = *(const ulonglong2*)&Bs[k][tx * 8 + 4];
            #pragma unroll
            for (int i = 0; i < 4; i++) {
                ffma2(acc[i][0], ad[i], b01.x);
                ffma2(acc[i][1], ad[i], b01.y);
                ffma2(acc[i][2], ad[i], b23.x);
                ffma2(acc[i][3], ad[i], b23.y);
            }
        }
        __syncthreads();
    }

    // epilogue: unpack pairs, bias + optional relu, float4 stores
    int colb = col0 + tx * 8;
    float bb[8];
    #pragma unroll
    for (int j = 0; j < 8; j++) bb[j] = bias[colb + j];

    #pragma unroll
    for (int i = 0; i < 4; i++) {
        int row = row0 + ty * 4 + i;
        if (row >= M) continue;
        float out[8];
        #pragma unroll
        for (int p = 0; p < 4; p++) {
            float2 c = *(float2*)&acc[i][p];
            out[2 * p]     = c.x + bb[2 * p];
            out[2 * p + 1] = c.y + bb[2 * p + 1];
        }
        if (doRelu) {
            #pragma unroll
            for (int j = 0; j < 8; j++) out[j] = fmaxf(out[j], 0.f);
        }
        float* cp = C + (size_t)row * N + colb;
        *(float4*)cp       = make_float4(out[0], out[1], out[2], out[3]);
        *(float4*)(cp + 4) = make_float4(out[4], out[5], out[6], out[7]);
    }
}

// ============================================================================
// Edge kernel (unchanged, 50us known-good): one warp per strip of EPW edges.
// ============================================================================
__global__ __launch_bounds__(256)
void edge_kernel(const float* __restrict__ ew,
                 const int* __restrict__ snd, const int* __restrict__ rcv,
                 int E, int G) {
    int lane = threadIdx.x & 31;
    int wl = threadIdx.x >> 5;
    int warp = blockIdx.x * 8 + wl;
    int base = warp * EPW;
    if (base >= E) return;
    int end = min(base + EPW, E);

    int lo = 0, hi = G;
    while (hi - lo > 1) {
        int mid = (lo + hi) >> 1;
        if (g_eoff[mid] <= base) lo = mid; else hi = mid;
    }
    int gid = lo;
    int bnd = g_eoff[gid + 1];

    const float* __restrict__ h = g_h;
    float acc = 0.f, wacc = 0.f;
    int e = base;
    for (;;) {
        int seg = min(end, bnd);
        #pragma unroll 4
        for (; e < seg; e++) {
            int s = __ldg(snd + e);
            int r = __ldg(rcv + e);
            float w = __ldg(ew + e);
            float4 a = *(const float4*)(h + (size_t)s * DF + lane * 4);
            float4 b = *(const float4*)(h + (size_t)r * DF + lane * 4);
            float d0 = a.x - b.x, d1 = a.y - b.y;
            float d2 = a.z - b.z, d3 = a.w - b.w;
            acc += w * (d0 * d0 + d1 * d1 + d2 * d2 + d3 * d3);
            if (lane == 0) wacc += w;
        }
        float v = acc;
        #pragma unroll
        for (int off = 16; off; off >>= 1)
            v += __shfl_xor_sync(0xffffffffu, v, off);
        if (lane == 0) {
            atomicAdd(&g_esum[gid], v);
            atomicAdd(&g_wsum[gid], wacc);
        }
        if (e >= end) break;
        acc = 0.f; wacc = 0.f;
        gid++;
        bnd = g_eoff[gid + 1];
    }
}

// ============================================================================
// Output kernel: gather node_out rows; block 0 computes the mean loss.
// ============================================================================
__global__ void out_kernel(float* __restrict__ out, int G, int lossIdx) {
    int g = blockIdx.x;
    int t = threadIdx.x;
    if (g < G)
        out[g * DF + t] = g_h[(size_t)g_nid[g] * DF + t];
    if (g == 0) {
        __shared__ float red[128];
        float term = 0.f;
        if (t < G) {
            float w = g_wsum[t];
            term = (w != 0.f) ? (g_esum[t] / w) : 0.f;
        }
        red[t] = term;
        __syncthreads();
        #pragma unroll
        for (int s = 64; s; s >>= 1) {
            if (t < s) red[t] += red[t + s];
            __syncthreads();
        }
        if (t == 0) out[lossIdx] = red[0] / (float)G;
    }
}

// ============================================================================
extern "C" void kernel_launch(void* const* d_in, const int* in_sizes, int n_in,
                              void* d_out, int out_size) {
    const float* nodes     = (const float*)d_in[0];
    const float* edges     = (const float*)d_in[1];
    const int*   senders   = (const int*)d_in[2];
    const int*   receivers = (const int*)d_in[3];
    const int*   n_node    = (const int*)d_in[4];
    const int*   n_edge    = (const int*)d_in[5];
    const float* W1        = (const float*)d_in[6];
    const float* b1        = (const float*)d_in[7];
    const float* W2        = (const float*)d_in[8];
    const float* b2        = (const float*)d_in[9];
    float* out = (float*)d_out;

    int M = in_sizes[0] / DF;
    int E = in_sizes[2];
    int G = in_sizes[4];

    void *p_tmp = nullptr, *p_h = nullptr;
    cudaGetSymbolAddress(&p_tmp, g_tmp);
    cudaGetSymbolAddress(&p_h, g_h);

    prefix_kernel<<<1, 128>>>(n_node, n_edge, G);

    dim3 g1(DH / BN, (M + BM - 1) / BM);
    gemm_bias_act<<<g1, 256>>>(nodes, W1, b1, (float*)p_tmp, M, DH, DF, 1);

    dim3 g2(DF / BN, (M + BM - 1) / BM);
    gemm_bias_act<<<g2, 256>>>((float*)p_tmp, W2, b2, (float*)p_h, M, DF, DH, 0);

    int eblocks = (E + EPW * 8 - 1) / (EPW * 8);
    edge_kernel<<<eblocks, 256>>>(edges, senders, receivers, E, G);

    out_kernel<<<G, 128>>>(out, G, out_size - 1);
}

// round 6
// speedup vs baseline: 1.5318x; 1.5318x over previous
#include <cuda_runtime.h>
#include <cuda_bf16.h>
#include <cstdint>

#define DF 128          // feature dim
#define DH 512          // hidden dim
#define MAXN 10000      // nodes
#define MAXG 128        // >= n_graphs (100)
#define EPW 32          // edges per warp strip

// -------- static device scratch (no allocations allowed) --------
__device__ float g_tmp[MAXN * DH];          // relu(nodes@W1+b1)
__device__ float g_h[MAXN * DF];            // final node features (fp32, exact)
__device__ __nv_bfloat16 g_hb[MAXN * DF];   // bf16 mirror for edge gather (2.5MB)
__device__ float g_wsum[MAXG];
__device__ float g_esum[MAXG];
__device__ int   g_eoff[MAXG + 1];
__device__ int   g_nid[MAXG];

// ============================================================================
// Kernel 0: prefix sums + zero accumulators (runs every replay)
// ============================================================================
__global__ void prefix_kernel(const int* __restrict__ n_node,
                              const int* __restrict__ n_edge, int G) {
    int t = threadIdx.x;
    if (t < MAXG) { g_wsum[t] = 0.f; g_esum[t] = 0.f; }
    if (t == 0) {
        int ea = 0, na = 0;
        g_eoff[0] = 0;
        for (int g = 0; g < G; g++) {
            ea += n_edge[g]; g_eoff[g + 1] = ea;
            na += n_node[g]; g_nid[g] = na - 1;
        }
    }
}

// ============================================================================
// Tiled SGEMM (R3 known-good SIMT): C = act(A@B + bias)
// 64x64 tile, BK=32, 256 threads, 4x4 micro-tile.
// If Cb != nullptr, also writes a bf16 mirror of C.
// ============================================================================
__global__ __launch_bounds__(256)
void gemm_bias_act(const float* __restrict__ A, const float* __restrict__ B,
                   const float* __restrict__ bias, float* __restrict__ C,
                   __nv_bfloat16* __restrict__ Cb,
                   int M, int N, int K, int doRelu) {
    const int BM = 64, BN = 64, BK = 32;
    __shared__ float As[BM][BK + 4];
    __shared__ float Bs[BK][BN + 4];

    int tid = threadIdx.x;
    int tx = tid & 15;
    int ty = tid >> 4;
    int row0 = blockIdx.y * BM;
    int col0 = blockIdx.x * BN;

    float acc[4][4] = {};

    for (int k0 = 0; k0 < K; k0 += BK) {
        #pragma unroll
        for (int i = 0; i < 2; i++) {
            int lin = tid + i * 256;
            int r = lin >> 3;
            int c4 = (lin & 7) * 4;
            int row = row0 + r;
            float4 v = make_float4(0.f, 0.f, 0.f, 0.f);
            if (row < M)
                v = *(const float4*)(A + (size_t)row * K + k0 + c4);
            *(float4*)&As[r][c4] = v;
        }
        #pragma unroll
        for (int i = 0; i < 2; i++) {
            int lin = tid + i * 256;
            int kk = lin >> 4;
            int c4 = (lin & 15) * 4;
            float4 v = *(const float4*)(B + (size_t)(k0 + kk) * N + col0 + c4);
            *(float4*)&Bs[kk][c4] = v;
        }
        __syncthreads();

        #pragma unroll
        for (int k = 0; k < BK; k++) {
            float4 b4 = *(const float4*)&Bs[k][tx * 4];
            #pragma unroll
            for (int i = 0; i < 4; i++) {
                float a = As[ty * 4 + i][k];
                acc[i][0] += a * b4.x;
                acc[i][1] += a * b4.y;
                acc[i][2] += a * b4.z;
                acc[i][3] += a * b4.w;
            }
        }
        __syncthreads();
    }

    #pragma unroll
    for (int i = 0; i < 4; i++) {
        int row = row0 + ty * 4 + i;
        if (row >= M) continue;
        float o[4];
        #pragma unroll
        for (int j = 0; j < 4; j++) {
            int col = col0 + tx * 4 + j;
            float v = acc[i][j] + bias[col];
            if (doRelu) v = fmaxf(v, 0.f);
            o[j] = v;
            C[(size_t)row * N + col] = v;
        }
        if (Cb) {
            // 4 bf16 = 8B aligned store (col base = tx*4, multiple of 4)
            __nv_bfloat162 p0 = __floats2bfloat162_rn(o[0], o[1]);
            __nv_bfloat162 p1 = __floats2bfloat162_rn(o[2], o[3]);
            uint2 pk = make_uint2(*(unsigned*)&p0, *(unsigned*)&p1);
            *(uint2*)(Cb + (size_t)row * N + col0 + tx * 4) = pk;
        }
    }
}

// ============================================================================
// Edge kernel v3: bf16 gather. One warp per strip of EPW edges.
// Lane l owns 4 bf16 features (8B) of each 128-feat row; accumulates
// w_e * partial_dist2 in fp32 across the strip; warp-reduce + atomics
// only once per graph-segment per strip.
// ============================================================================
__global__ __launch_bounds__(256)
void edge_kernel(const float* __restrict__ ew,
                 const int* __restrict__ snd, const int* __restrict__ rcv,
                 int E, int G) {
    int lane = threadIdx.x & 31;
    int wl = threadIdx.x >> 5;
    int warp = blockIdx.x * 8 + wl;
    int base = warp * EPW;
    if (base >= E) return;
    int end = min(base + EPW, E);

    int lo = 0, hi = G;
    while (hi - lo > 1) {
        int mid = (lo + hi) >> 1;
        if (g_eoff[mid] <= base) lo = mid; else hi = mid;
    }
    int gid = lo;
    int bnd = g_eoff[gid + 1];

    const __nv_bfloat16* __restrict__ hb = g_hb;
    float acc = 0.f, wacc = 0.f;
    int e = base;
    for (;;) {
        int seg = min(end, bnd);
        #pragma unroll 4
        for (; e < seg; e++) {
            int s = __ldg(snd + e);
            int r = __ldg(rcv + e);
            float w = __ldg(ew + e);
            uint2 av = *(const uint2*)(hb + (size_t)s * DF + lane * 4);
            uint2 bv = *(const uint2*)(hb + (size_t)r * DF + lane * 4);
            float2 a0 = __bfloat1622float2(*(__nv_bfloat162*)&av.x);
            float2 a1 = __bfloat1622float2(*(__nv_bfloat162*)&av.y);
            float2 b0 = __bfloat1622float2(*(__nv_bfloat162*)&bv.x);
            float2 b1 = __bfloat1622float2(*(__nv_bfloat162*)&bv.y);
            float d0 = a0.x - b0.x, d1 = a0.y - b0.y;
            float d2 = a1.x - b1.x, d3 = a1.y - b1.y;
            acc += w * (d0 * d0 + d1 * d1 + d2 * d2 + d3 * d3);
            if (lane == 0) wacc += w;
        }
        float v = acc;
        #pragma unroll
        for (int off = 16; off; off >>= 1)
            v += __shfl_xor_sync(0xffffffffu, v, off);
        if (lane == 0) {
            atomicAdd(&g_esum[gid], v);
            atomicAdd(&g_wsum[gid], wacc);
        }
        if (e >= end) break;
        acc = 0.f; wacc = 0.f;
        gid++;
        bnd = g_eoff[gid + 1];
    }
}

// ============================================================================
// Output kernel: gather node_out rows (exact fp32); block 0 computes loss.
// ============================================================================
__global__ void out_kernel(float* __restrict__ out, int G, int lossIdx) {
    int g = blockIdx.x;
    int t = threadIdx.x;
    if (g < G)
        out[g * DF + t] = g_h[(size_t)g_nid[g] * DF + t];
    if (g == 0) {
        __shared__ float red[128];
        float term = 0.f;
        if (t < G) {
            float w = g_wsum[t];
            term = (w != 0.f) ? (g_esum[t] / w) : 0.f;
        }
        red[t] = term;
        __syncthreads();
        #pragma unroll
        for (int s = 64; s; s >>= 1) {
            if (t < s) red[t] += red[t + s];
            __syncthreads();
        }
        if (t == 0) out[lossIdx] = red[0] / (float)G;
    }
}

// ============================================================================
extern "C" void kernel_launch(void* const* d_in, const int* in_sizes, int n_in,
                              void* d_out, int out_size) {
    const float* nodes     = (const float*)d_in[0];
    const float* edges     = (const float*)d_in[1];
    const int*   senders   = (const int*)d_in[2];
    const int*   receivers = (const int*)d_in[3];
    const int*   n_node    = (const int*)d_in[4];
    const int*   n_edge    = (const int*)d_in[5];
    const float* W1        = (const float*)d_in[6];
    const float* b1        = (const float*)d_in[7];
    const float* W2        = (const float*)d_in[8];
    const float* b2        = (const float*)d_in[9];
    float* out = (float*)d_out;

    int M = in_sizes[0] / DF;
    int E = in_sizes[2];
    int G = in_sizes[4];

    void *p_tmp = nullptr, *p_h = nullptr, *p_hb = nullptr;
    cudaGetSymbolAddress(&p_tmp, g_tmp);
    cudaGetSymbolAddress(&p_h, g_h);
    cudaGetSymbolAddress(&p_hb, g_hb);

    prefix_kernel<<<1, 128>>>(n_node, n_edge, G);

    dim3 g1(DH / 64, (M + 63) / 64);
    gemm_bias_act<<<g1, 256>>>(nodes, W1, b1, (float*)p_tmp, nullptr,
                               M, DH, DF, 1);

    dim3 g2(DF / 64, (M + 63) / 64);
    gemm_bias_act<<<g2, 256>>>((float*)p_tmp, W2, b2, (float*)p_h,
                               (__nv_bfloat16*)p_hb, M, DF, DH, 0);

    int eblocks = (E + EPW * 8 - 1) / (EPW * 8);
    edge_kernel<<<eblocks, 256>>>(edges, senders, receivers, E, G);

    out_kernel<<<G, 128>>>(out, G, out_size - 1);
}

// round 8
// speedup vs baseline: 1.5802x; 1.0316x over previous
#include <cuda_runtime.h>
#include <cuda_bf16.h>
#include <cstdint>

#define DF 128          // feature dim
#define DH 512          // hidden dim
#define MAXN 10000      // nodes
#define MAXG 128        // >= n_graphs (100)
#define EPW 32          // edges per warp strip

// -------- static device scratch (no allocations allowed) --------
__device__ float g_tmp[MAXN * DH];          // relu(nodes@W1+b1)
__device__ float g_h[MAXN * DF];            // final node features (fp32, exact)
__device__ __nv_bfloat16 g_hb[MAXN * DF];   // bf16 mirror for edge gather (2.5MB)
__device__ float g_wsum[MAXG];
__device__ float g_esum[MAXG];
__device__ int   g_eoff[MAXG + 1];
__device__ int   g_nid[MAXG];

// ============================================================================
// Kernel 0: prefix sums + zero accumulators (runs every replay)
// ============================================================================
__global__ void prefix_kernel(const int* __restrict__ n_node,
                              const int* __restrict__ n_edge, int G) {
    int t = threadIdx.x;
    if (t < MAXG) { g_wsum[t] = 0.f; g_esum[t] = 0.f; }
    if (t == 0) {
        int ea = 0, na = 0;
        g_eoff[0] = 0;
        for (int g = 0; g < G; g++) {
            ea += n_edge[g]; g_eoff[g + 1] = ea;
            na += n_node[g]; g_nid[g] = na - 1;
        }
    }
}

// ============================================================================
// Tiled SGEMM (known-good SIMT): C = act(A@B + bias)
// 64x64 tile, BK=32, 256 threads, 4x4 micro-tile.
// If Cb != nullptr, also writes a bf16 mirror of C.
// ============================================================================
__global__ __launch_bounds__(256)
void gemm_bias_act(const float* __restrict__ A, const float* __restrict__ B,
                   const float* __restrict__ bias, float* __restrict__ C,
                   __nv_bfloat16* __restrict__ Cb,
                   int M, int N, int K, int doRelu) {
    const int BM = 64, BN = 64, BK = 32;
    __shared__ float As[BM][BK + 4];
    __shared__ float Bs[BK][BN + 4];

    int tid = threadIdx.x;
    int tx = tid & 15;
    int ty = tid >> 4;
    int row0 = blockIdx.y * BM;
    int col0 = blockIdx.x * BN;

    float acc[4][4] = {};

    for (int k0 = 0; k0 < K; k0 += BK) {
        #pragma unroll
        for (int i = 0; i < 2; i++) {
            int lin = tid + i * 256;
            int r = lin >> 3;
            int c4 = (lin & 7) * 4;
            int row = row0 + r;
            float4 v = make_float4(0.f, 0.f, 0.f, 0.f);
            if (row < M)
                v = *(const float4*)(A + (size_t)row * K + k0 + c4);
            *(float4*)&As[r][c4] = v;
        }
        #pragma unroll
        for (int i = 0; i < 2; i++) {
            int lin = tid + i * 256;
            int kk = lin >> 4;
            int c4 = (lin & 15) * 4;
            float4 v = *(const float4*)(B + (size_t)(k0 + kk) * N + col0 + c4);
            *(float4*)&Bs[kk][c4] = v;
        }
        __syncthreads();

        #pragma unroll
        for (int k = 0; k < BK; k++) {
            float4 b4 = *(const float4*)&Bs[k][tx * 4];
            #pragma unroll
            for (int i = 0; i < 4; i++) {
                float a = As[ty * 4 + i][k];
                acc[i][0] += a * b4.x;
                acc[i][1] += a * b4.y;
                acc[i][2] += a * b4.z;
                acc[i][3] += a * b4.w;
            }
        }
        __syncthreads();
    }

    #pragma unroll
    for (int i = 0; i < 4; i++) {
        int row = row0 + ty * 4 + i;
        if (row >= M) continue;
        float o[4];
        #pragma unroll
        for (int j = 0; j < 4; j++) {
            int col = col0 + tx * 4 + j;
            float v = acc[i][j] + bias[col];
            if (doRelu) v = fmaxf(v, 0.f);
            o[j] = v;
            C[(size_t)row * N + col] = v;
        }
        if (Cb) {
            __nv_bfloat162 p0 = __floats2bfloat162_rn(o[0], o[1]);
            __nv_bfloat162 p1 = __floats2bfloat162_rn(o[2], o[3]);
            uint2 pk = make_uint2(*(unsigned*)&p0, *(unsigned*)&p1);
            *(uint2*)(Cb + (size_t)row * N + col0 + tx * 4) = pk;
        }
    }
}

// ============================================================================
// Edge kernel v4: bf16 gather + packed bf16 subtract + shift-unpack.
// Per lane-edge: 2 LDG.64, 2 sub.rn.bf16x2, 4 ALU unpack, 5 FFMA.
// (sub of close bf16 values is exact by Sterbenz; worst-case error matches
//  the storage rounding already measured at rel_err ~1e-5.)
// ============================================================================
__global__ __launch_bounds__(256)
void edge_kernel(const float* __restrict__ ew,
                 const int* __restrict__ snd, const int* __restrict__ rcv,
                 int E, int G) {
    int lane = threadIdx.x & 31;
    int wl = threadIdx.x >> 5;
    int warp = blockIdx.x * 8 + wl;
    int base = warp * EPW;
    if (base >= E) return;
    int end = min(base + EPW, E);

    int lo = 0, hi = G;
    while (hi - lo > 1) {
        int mid = (lo + hi) >> 1;
        if (g_eoff[mid] <= base) lo = mid; else hi = mid;
    }
    int gid = lo;
    int bnd = g_eoff[gid + 1];

    const __nv_bfloat16* __restrict__ hb = g_hb;
    float acc = 0.f, wacc = 0.f;
    int e = base;
    for (;;) {
        int seg = min(end, bnd);
        #pragma unroll 4
        for (; e < seg; e++) {
            int s = __ldg(snd + e);
            int r = __ldg(rcv + e);
            float w = __ldg(ew + e);
            uint2 av = *(const uint2*)(hb + (size_t)s * DF + lane * 4);
            uint2 bv = *(const uint2*)(hb + (size_t)r * DF + lane * 4);
            unsigned d0, d1;
            asm("sub.rn.bf16x2 %0, %1, %2;" : "=r"(d0) : "r"(av.x), "r"(bv.x));
            asm("sub.rn.bf16x2 %0, %1, %2;" : "=r"(d1) : "r"(av.y), "r"(bv.y));
            // bf16 -> fp32 exactly via bit placement (no F2F)
            float f0 = __uint_as_float(d0 << 16);
            float f1 = __uint_as_float(d0 & 0xFFFF0000u);
            float f2 = __uint_as_float(d1 << 16);
            float f3 = __uint_as_float(d1 & 0xFFFF0000u);
            float t = f0 * f0;
            t = fmaf(f1, f1, t);
            t = fmaf(f2, f2, t);
            t = fmaf(f3, f3, t);
            acc = fmaf(w, t, acc);
            if (lane == 0) wacc += w;
        }
        float v = acc;
        #pragma unroll
        for (int off = 16; off; off >>= 1)
            v += __shfl_xor_sync(0xffffffffu, v, off);
        if (lane == 0) {
            atomicAdd(&g_esum[gid], v);
            atomicAdd(&g_wsum[gid], wacc);
        }
        if (e >= end) break;
        acc = 0.f; wacc = 0.f;
        gid++;
        bnd = g_eoff[gid + 1];
    }
}

// ============================================================================
// Output kernel: gather node_out rows (exact fp32); block 0 computes loss.
// ============================================================================
__global__ void out_kernel(float* __restrict__ out, int G, int lossIdx) {
    int g = blockIdx.x;
    int t = threadIdx.x;
    if (g < G)
        out[g * DF + t] = g_h[(size_t)g_nid[g] * DF + t];
    if (g == 0) {
        __shared__ float red[128];
        float term = 0.f;
        if (t < G) {
            float w = g_wsum[t];
            term = (w != 0.f) ? (g_esum[t] / w) : 0.f;
        }
        red[t] = term;
        __syncthreads();
        #pragma unroll
        for (int s = 64; s; s >>= 1) {
            if (t < s) red[t] += red[t + s];
            __syncthreads();
        }
        if (t == 0) out[lossIdx] = red[0] / (float)G;
    }
}

// ============================================================================
extern "C" void kernel_launch(void* const* d_in, const int* in_sizes, int n_in,
                              void* d_out, int out_size) {
    const float* nodes     = (const float*)d_in[0];
    const float* edges     = (const float*)d_in[1];
    const int*   senders   = (const int*)d_in[2];
    const int*   receivers = (const int*)d_in[3];
    const int*   n_node    = (const int*)d_in[4];
    const int*   n_edge    = (const int*)d_in[5];
    const float* W1        = (const float*)d_in[6];
    const float* b1        = (const float*)d_in[7];
    const float* W2        = (const float*)d_in[8];
    const float* b2        = (const float*)d_in[9];
    float* out = (float*)d_out;

    int M = in_sizes[0] / DF;
    int E = in_sizes[2];
    int G = in_sizes[4];

    void *p_tmp = nullptr, *p_h = nullptr, *p_hb = nullptr;
    cudaGetSymbolAddress(&p_tmp, g_tmp);
    cudaGetSymbolAddress(&p_h, g_h);
    cudaGetSymbolAddress(&p_hb, g_hb);

    prefix_kernel<<<1, 128>>>(n_node, n_edge, G);

    dim3 g1(DH / 64, (M + 63) / 64);
    gemm_bias_act<<<g1, 256>>>(nodes, W1, b1, (float*)p_tmp, nullptr,
                               M, DH, DF, 1);

    dim3 g2(DF / 64, (M + 63) / 64);
    gemm_bias_act<<<g2, 256>>>((float*)p_tmp, W2, b2, (float*)p_h,
                               (__nv_bfloat16*)p_hb, M, DF, DH, 0);

    int eblocks = (E + EPW * 8 - 1) / (EPW * 8);
    edge_kernel<<<eblocks, 256>>>(edges, senders, receivers, E, G);

    out_kernel<<<G, 128>>>(out, G, out_size - 1);
}